// round 1
// baseline (speedup 1.0000x reference)
#include <cuda_runtime.h>

#define BB 32
#define NN 1024
#define FF 7
#define HID 256
#define MLPH 64
#define OUTD 8
#define THR2 0.09f

// ---- device scratch (no allocations allowed) ----
__device__ unsigned g_adj[BB * NN * 32];   // adjacency bitmask, 4MB
__device__ float    g_dinv[BB * NN];       // 1/sqrt(degree)
__device__ unsigned g_maxd2u[BB];          // max dist^2 as uint bits (nonneg float ordering)
__device__ float    g_upart[BB * 4 * HID]; // per-chunk partial of sum_j s_j * h_j
__device__ float    g_speedp[BB * 4];      // per-chunk partial speed sums
__device__ float    g_y1[BB * MLPH];       // MLP branch output

__global__ void k0_init() {
    if (threadIdx.x < BB) g_maxd2u[threadIdx.x] = 0u;
}

// K1: pairwise distances -> adjacency bits, degree->dinv, per-batch max dist^2.
// block = 256 thr, 8 warps; each warp owns 8 rows; 16 blocks per batch.
__global__ void k1_pairs(const float* __restrict__ x) {
    __shared__ float2 s_pts[NN];
    __shared__ float  s_max[8];
    int b = blockIdx.x >> 4;
    int rowbase = (blockIdx.x & 15) << 6;     // 64 rows per block
    int t = threadIdx.x, lane = t & 31, w = t >> 5;

    for (int j = t; j < NN; j += 256) {
        const float* xr = x + ((size_t)b * NN + j) * FF;
        s_pts[j] = make_float2(xr[1], xr[2]);
    }
    __syncthreads();

    int i0 = rowbase + w * 8;
    float xi[8], yi[8]; unsigned word[8];
#pragma unroll
    for (int r = 0; r < 8; ++r) {
        float2 p = s_pts[i0 + r]; xi[r] = p.x; yi[r] = p.y; word[r] = 0u;
    }
    float mx = 0.f;
    for (int jw = 0; jw < 32; ++jw) {
        float2 pj = s_pts[jw * 32 + lane];
#pragma unroll
        for (int r = 0; r < 8; ++r) {
            float dx = xi[r] - pj.x, dy = yi[r] - pj.y;
            float d2 = fmaf(dx, dx, dy * dy);
            mx = fmaxf(mx, d2);
            unsigned m = __ballot_sync(0xffffffffu, d2 < THR2);
            if (lane == jw) word[r] = m;
        }
    }
#pragma unroll
    for (int r = 0; r < 8; ++r) {
        int i = i0 + r;
        g_adj[((size_t)b * NN + i) * 32 + lane] = word[r];
        int deg = __reduce_add_sync(0xffffffffu, __popc(word[r]));
        if (lane == 0) g_dinv[b * NN + i] = rsqrtf((float)deg);
    }
    for (int o = 16; o > 0; o >>= 1)
        mx = fmaxf(mx, __shfl_xor_sync(0xffffffffu, mx, o));
    if (lane == 0) s_max[w] = mx;
    __syncthreads();
    if (t == 0) {
        float m = s_max[0];
#pragma unroll
        for (int k = 1; k < 8; ++k) m = fmaxf(m, s_max[k]);
        atomicMax(&g_maxd2u[b], __float_as_uint(m));
    }
}

// K2: sparse graph pass. Per block: one batch, 256 rows (4 chunks/batch).
// Phase A: P_i = dinv_i * sum_{j in adj(i)} dinv_j * pts_j ; s_i = dinv_i * sum dinv_j.
// Phase B: partial u_k = sum_i s_i * relu(W1[k].P_i + b1[k])  (thread k).
// Also deterministic per-chunk speed sums.
__global__ void k2_gcn(const float* __restrict__ x,
                       const float* __restrict__ W1, const float* __restrict__ b1) {
    __shared__ float2 s_pts[NN];
    __shared__ float  s_dinv[NN];
    __shared__ float  sPx[256], sPy[256], sS[256], sred[256];
    int b = blockIdx.x >> 2, chunk = blockIdx.x & 3;
    int t = threadIdx.x;

    for (int j = t; j < NN; j += 256) {
        const float* xr = x + ((size_t)b * NN + j) * FF;
        s_pts[j]  = make_float2(xr[1], xr[2]);
        s_dinv[j] = g_dinv[b * NN + j];
    }
    __syncthreads();

    int i = chunk * 256 + t;
    float di = s_dinv[i];
    float wsum = 0.f, px = 0.f, py = 0.f;
    const unsigned* arow = g_adj + ((size_t)b * NN + i) * 32;
#pragma unroll 4
    for (int wd = 0; wd < 32; ++wd) {
        unsigned m = arow[wd];
        int base = wd * 32;
        while (m) {
            int j = base + __ffs(m) - 1;
            m &= m - 1;
            float dj = s_dinv[j];
            float2 pj = s_pts[j];
            wsum += dj;
            px = fmaf(dj, pj.x, px);
            py = fmaf(dj, pj.y, py);
        }
    }
    sS[t]  = di * wsum;
    sPx[t] = di * px;
    sPy[t] = di * py;

    const float* xr = x + ((size_t)b * NN + i) * FF;
    float s3 = xr[3], s4 = xr[4];
    sred[t] = sqrtf(fmaf(s3, s3, s4 * s4));
    __syncthreads();
    for (int o = 128; o > 0; o >>= 1) {
        if (t < o) sred[t] += sred[t + o];
        __syncthreads();
    }
    if (t == 0) g_speedp[b * 4 + chunk] = sred[0];

    float w10 = W1[t * 2], w11 = W1[t * 2 + 1], bk = b1[t];
    float acc = 0.f;
#pragma unroll 8
    for (int r = 0; r < 256; ++r) {
        float h = fmaf(w10, sPx[r], fmaf(w11, sPy[r], bk));
        h = fmaxf(h, 0.f);
        acc = fmaf(sS[r], h, acc);
    }
    g_upart[(b * 4 + chunk) * HID + t] = acc;
}

// K_mlp: per-batch flat MLP: [7168] -> relu 64 -> relu 64. One block per batch.
__global__ void k_mlp(const float* __restrict__ x,
                      const float* __restrict__ Wm0, const float* __restrict__ bm0,
                      const float* __restrict__ Wm1, const float* __restrict__ bm1) {
    __shared__ float sx[NN * FF];
    __shared__ float sy0[MLPH];
    int b = blockIdx.x, t = threadIdx.x;
    const float4* xb  = (const float4*)(x + (size_t)b * NN * FF);
    float4* sx4 = (float4*)sx;
    for (int j = t; j < NN * FF / 4; j += 256) sx4[j] = xb[j];
    __syncthreads();

    int h = t >> 2, q = t & 3;
    const float4* wr  = (const float4*)(Wm0 + (size_t)h * NN * FF);
    const float4* sxv = (const float4*)sx;
    float acc = 0.f;
    for (int k = q; k < NN * FF / 4; k += 4) {
        float4 wv = wr[k], xv = sxv[k];
        acc = fmaf(wv.x, xv.x, acc);
        acc = fmaf(wv.y, xv.y, acc);
        acc = fmaf(wv.z, xv.z, acc);
        acc = fmaf(wv.w, xv.w, acc);
    }
    acc += __shfl_down_sync(0xffffffffu, acc, 2, 4);
    acc += __shfl_down_sync(0xffffffffu, acc, 1, 4);
    if (q == 0) sy0[h] = fmaxf(acc + bm0[h], 0.f);
    __syncthreads();

    if (t < MLPH) {
        float a = bm1[t];
        const float* w = Wm1 + t * MLPH;
#pragma unroll 8
        for (int j = 0; j < MLPH; ++j) a = fmaf(w[j], sy0[j], a);
        g_y1[b * MLPH + t] = fmaxf(a, 0.f);
    }
}

// K3: per-batch finals: u/N -> W2 -> Wfc ; global branch ; concat -> Wp.
__global__ void k3_final(const float* __restrict__ W2,  const float* __restrict__ b2,
                         const float* __restrict__ Wfc, const float* __restrict__ bfc,
                         const float* __restrict__ Wg,  const float* __restrict__ bg,
                         const float* __restrict__ Wp,  const float* __restrict__ bp,
                         float* __restrict__ out) {
    __shared__ float sm[HID], smid[HID], sgcn[HID], sglo[OUTD], sy1[MLPH];
    int b = blockIdx.x, t = threadIdx.x;

    float u = g_upart[(b * 4 + 0) * HID + t] + g_upart[(b * 4 + 1) * HID + t]
            + g_upart[(b * 4 + 2) * HID + t] + g_upart[(b * 4 + 3) * HID + t];
    sm[t] = u * (1.0f / 1024.0f);
    if (t < MLPH) sy1[t] = g_y1[b * MLPH + t];
    __syncthreads();

    float a = b2[t];
    const float4* w2r = (const float4*)(W2 + (size_t)t * HID);
    const float4* smv = (const float4*)sm;
#pragma unroll 8
    for (int j = 0; j < HID / 4; ++j) {
        float4 wv = w2r[j], mv = smv[j];
        a = fmaf(wv.x, mv.x, a); a = fmaf(wv.y, mv.y, a);
        a = fmaf(wv.z, mv.z, a); a = fmaf(wv.w, mv.w, a);
    }
    smid[t] = a;
    __syncthreads();

    a = bfc[t];
    const float4* wfr  = (const float4*)(Wfc + (size_t)t * HID);
    const float4* smdv = (const float4*)smid;
#pragma unroll 8
    for (int j = 0; j < HID / 4; ++j) {
        float4 wv = wfr[j], mv = smdv[j];
        a = fmaf(wv.x, mv.x, a); a = fmaf(wv.y, mv.y, a);
        a = fmaf(wv.z, mv.z, a); a = fmaf(wv.w, mv.w, a);
    }
    sgcn[t] = a;

    if (t < OUTD) {
        float avg = (g_speedp[b * 4 + 0] + g_speedp[b * 4 + 1]
                   + g_speedp[b * 4 + 2] + g_speedp[b * 4 + 3]) * (1.0f / 1024.0f);
        float den = rsqrtf(__uint_as_float(g_maxd2u[b]));   // 1/max(dist)
        sglo[t] = fmaxf(fmaf(Wg[t * 2], avg, fmaf(Wg[t * 2 + 1], den, bg[t])), 0.f);
    }
    __syncthreads();

    if (t < OUTD) {
        float o = bp[t];
        const float* wp = Wp + t * (MLPH + HID + OUTD);
#pragma unroll 8
        for (int j = 0; j < MLPH; ++j) o = fmaf(wp[j], sy1[j], o);
#pragma unroll 8
        for (int j = 0; j < HID;  ++j) o = fmaf(wp[MLPH + j], sgcn[j], o);
#pragma unroll
        for (int j = 0; j < OUTD; ++j) o = fmaf(wp[MLPH + HID + j], sglo[j], o);
        out[b * OUTD + t] = o;
    }
}

extern "C" void kernel_launch(void* const* d_in, const int* in_sizes, int n_in,
                              void* d_out, int out_size) {
    const float* x   = (const float*)d_in[0];
    const float* W1  = (const float*)d_in[1];
    const float* b1  = (const float*)d_in[2];
    const float* W2  = (const float*)d_in[3];
    const float* b2  = (const float*)d_in[4];
    const float* Wfc = (const float*)d_in[5];
    const float* bfc = (const float*)d_in[6];
    const float* Wg  = (const float*)d_in[7];
    const float* bg  = (const float*)d_in[8];
    const float* Wm0 = (const float*)d_in[9];
    const float* bm0 = (const float*)d_in[10];
    const float* Wm1 = (const float*)d_in[11];
    const float* bm1 = (const float*)d_in[12];
    const float* Wp  = (const float*)d_in[13];
    const float* bp  = (const float*)d_in[14];
    float* out = (float*)d_out;

    k0_init<<<1, 32>>>();
    k1_pairs<<<512, 256>>>(x);
    k2_gcn<<<128, 256>>>(x, W1, b1);
    k_mlp<<<32, 256>>>(x, Wm0, bm0, Wm1, bm1);
    k3_final<<<32, 256>>>(W2, b2, Wfc, bfc, Wg, bg, Wp, bp, out);
}

// round 2
// speedup vs baseline: 1.4051x; 1.4051x over previous
#include <cuda_runtime.h>

#define BB 32
#define NN 1024
#define FF 7
#define HID 256
#define MLPH 64
#define OUTD 8
#define THR2 0.09f
#define KCH 64          // number of K-chunks for MLP layer0
#define K4  28          // float4s per chunk (112 floats); 64*112 = 7168

// ---- device scratch ----
__device__ unsigned g_adj[BB * NN * 32];     // adjacency bitmask, 4MB
__device__ float    g_dinv[BB * NN];         // 1/sqrt(degree)
__device__ float    g_maxp[BB * 16];         // per-k1-block max dist^2 partials
__device__ float    g_upart[BB * 4 * HID];   // per-chunk partial of sum_j s_j * h_j
__device__ float    g_speedp[BB * 4];        // per-chunk partial speed sums
__device__ float    g_mpart[KCH * BB * MLPH];// MLP layer0 K-chunk partials

// ============================================================================
// kA: fused. Blocks [0,512): pairwise adjacency. Blocks [512,576): MLP0 chunks.
// ============================================================================
__global__ __launch_bounds__(256) void kA(const float* __restrict__ x,
                                          const float* __restrict__ Wm0) {
    __shared__ float sbuf[K4 * MLPH * 4 + K4 * BB * 4 + 16];   // 43KB
    int t = threadIdx.x;

    if (blockIdx.x < 512) {
        // ---------------- pairwise: 8 warps x 8 rows, 64 rows/block ----------
        float2* s_pts = (float2*)sbuf;              // [NN]
        float*  s_max = sbuf + 2 * NN;              // [8]
        int b = blockIdx.x >> 4;
        int blk16 = blockIdx.x & 15;
        int rowbase = blk16 << 6;
        int lane = t & 31, w = t >> 5;

        for (int j = t; j < NN; j += 256) {
            const float* xr = x + ((size_t)b * NN + j) * FF;
            s_pts[j] = make_float2(xr[1], xr[2]);
        }
        __syncthreads();

        int i0 = rowbase + w * 8;
        float xi[8], yi[8]; unsigned word[8];
#pragma unroll
        for (int r = 0; r < 8; ++r) {
            float2 p = s_pts[i0 + r]; xi[r] = p.x; yi[r] = p.y; word[r] = 0u;
        }
        float mx = 0.f;
        for (int jw = 0; jw < 32; ++jw) {
            float2 pj = s_pts[jw * 32 + lane];
#pragma unroll
            for (int r = 0; r < 8; ++r) {
                float dx = xi[r] - pj.x, dy = yi[r] - pj.y;
                float d2 = fmaf(dx, dx, dy * dy);
                mx = fmaxf(mx, d2);
                unsigned m = __ballot_sync(0xffffffffu, d2 < THR2);
                if (lane == jw) word[r] = m;
            }
        }
#pragma unroll
        for (int r = 0; r < 8; ++r) {
            int i = i0 + r;
            g_adj[((size_t)b * NN + i) * 32 + lane] = word[r];
            int deg = __reduce_add_sync(0xffffffffu, __popc(word[r]));
            if (lane == 0) g_dinv[b * NN + i] = rsqrtf((float)deg);
        }
        for (int o = 16; o > 0; o >>= 1)
            mx = fmaxf(mx, __shfl_xor_sync(0xffffffffu, mx, o));
        if (lane == 0) s_max[w] = mx;
        __syncthreads();
        if (t == 0) {
            float m = s_max[0];
#pragma unroll
            for (int k = 1; k < 8; ++k) m = fmaxf(m, s_max[k]);
            g_maxp[b * 16 + blk16] = m;
        }
    } else {
        // ---------------- MLP layer0 K-chunk GEMM partial --------------------
        int c = blockIdx.x - 512;
        float4* sw4 = (float4*)sbuf;                       // [K4][64]
        float4* sx4 = (float4*)(sbuf + K4 * MLPH * 4);     // [K4][32]
        const float4* W4 = (const float4*)Wm0;
        const float4* X4 = (const float4*)x;

        for (int i = t; i < MLPH * K4; i += 256) {         // 1792
            int h = i / K4, k = i % K4;
            sw4[k * MLPH + h] = W4[(size_t)h * 1792 + c * K4 + k];
        }
        for (int i = t; i < BB * K4; i += 256) {           // 896
            int b = i / K4, k = i % K4;
            sx4[k * BB + b] = X4[(size_t)b * 1792 + c * K4 + k];
        }
        __syncthreads();

        if (t < 128) {
            int hb = t & 15;       // heads hb + 16j
            int bb = t >> 4;       // batches bb + 8i
            float acc[4][4] = {};
#pragma unroll 4
            for (int k = 0; k < K4; ++k) {
                float4 xv[4], wv[4];
#pragma unroll
                for (int i = 0; i < 4; ++i) xv[i] = sx4[k * BB + bb + 8 * i];
#pragma unroll
                for (int j = 0; j < 4; ++j) wv[j] = sw4[k * MLPH + hb + 16 * j];
#pragma unroll
                for (int i = 0; i < 4; ++i)
#pragma unroll
                    for (int j = 0; j < 4; ++j) {
                        acc[i][j] = fmaf(xv[i].x, wv[j].x, acc[i][j]);
                        acc[i][j] = fmaf(xv[i].y, wv[j].y, acc[i][j]);
                        acc[i][j] = fmaf(xv[i].z, wv[j].z, acc[i][j]);
                        acc[i][j] = fmaf(xv[i].w, wv[j].w, acc[i][j]);
                    }
            }
#pragma unroll
            for (int i = 0; i < 4; ++i)
#pragma unroll
                for (int j = 0; j < 4; ++j)
                    g_mpart[((size_t)c * BB + bb + 8 * i) * MLPH + hb + 16 * j] = acc[i][j];
        }
    }
}

// ============================================================================
// K2: sparse graph pass (unchanged structure)
// ============================================================================
__global__ void k2_gcn(const float* __restrict__ x,
                       const float* __restrict__ W1, const float* __restrict__ b1) {
    __shared__ float2 s_pts[NN];
    __shared__ float  s_dinv[NN];
    __shared__ float  sPx[256], sPy[256], sS[256], sred[256];
    int b = blockIdx.x >> 2, chunk = blockIdx.x & 3;
    int t = threadIdx.x;

    for (int j = t; j < NN; j += 256) {
        const float* xr = x + ((size_t)b * NN + j) * FF;
        s_pts[j]  = make_float2(xr[1], xr[2]);
        s_dinv[j] = g_dinv[b * NN + j];
    }
    __syncthreads();

    int i = chunk * 256 + t;
    float di = s_dinv[i];
    float wsum = 0.f, px = 0.f, py = 0.f;
    const unsigned* arow = g_adj + ((size_t)b * NN + i) * 32;
#pragma unroll 4
    for (int wd = 0; wd < 32; ++wd) {
        unsigned m = arow[wd];
        int base = wd * 32;
        while (m) {
            int j = base + __ffs(m) - 1;
            m &= m - 1;
            float dj = s_dinv[j];
            float2 pj = s_pts[j];
            wsum += dj;
            px = fmaf(dj, pj.x, px);
            py = fmaf(dj, pj.y, py);
        }
    }
    sS[t]  = di * wsum;
    sPx[t] = di * px;
    sPy[t] = di * py;

    const float* xr = x + ((size_t)b * NN + i) * FF;
    float s3 = xr[3], s4 = xr[4];
    sred[t] = sqrtf(fmaf(s3, s3, s4 * s4));
    __syncthreads();
    for (int o = 128; o > 0; o >>= 1) {
        if (t < o) sred[t] += sred[t + o];
        __syncthreads();
    }
    if (t == 0) g_speedp[b * 4 + chunk] = sred[0];

    float w10 = W1[t * 2], w11 = W1[t * 2 + 1], bk = b1[t];
    float acc = 0.f;
#pragma unroll 8
    for (int r = 0; r < 256; ++r) {
        float h = fmaf(w10, sPx[r], fmaf(w11, sPy[r], bk));
        h = fmaxf(h, 0.f);
        acc = fmaf(sS[r], h, acc);
    }
    g_upart[(b * 4 + chunk) * HID + t] = acc;
}

// ============================================================================
// K3: per-batch finals: mlp reduce + Wm1, u/N -> W2 -> Wfc, global, concat->Wp.
// ============================================================================
__global__ void k3_final(const float* __restrict__ W2,  const float* __restrict__ b2,
                         const float* __restrict__ Wfc, const float* __restrict__ bfc,
                         const float* __restrict__ Wg,  const float* __restrict__ bg,
                         const float* __restrict__ Wm1, const float* __restrict__ bm1,
                         const float* __restrict__ bm0,
                         const float* __restrict__ Wp,  const float* __restrict__ bp,
                         float* __restrict__ out) {
    __shared__ float sm[HID], smid[HID], sgcn[HID], sglo[OUTD];
    __shared__ float sy0[MLPH], sy1[MLPH];
    int b = blockIdx.x, t = threadIdx.x;

    float u = g_upart[(b * 4 + 0) * HID + t] + g_upart[(b * 4 + 1) * HID + t]
            + g_upart[(b * 4 + 2) * HID + t] + g_upart[(b * 4 + 3) * HID + t];
    sm[t] = u * (1.0f / 1024.0f);

    // MLP chunk reduce (deterministic fixed order) + bias/relu
    if (t < MLPH) {
        float a = 0.f;
#pragma unroll 8
        for (int c = 0; c < KCH; ++c)
            a += g_mpart[((size_t)c * BB + b) * MLPH + t];
        sy0[t] = fmaxf(a + bm0[t], 0.f);
    }
    __syncthreads();

    // Wm1 layer
    if (t < MLPH) {
        float a = bm1[t];
        const float* w = Wm1 + t * MLPH;
#pragma unroll 8
        for (int j = 0; j < MLPH; ++j) a = fmaf(w[j], sy0[j], a);
        sy1[t] = fmaxf(a, 0.f);
    }

    // W2 matvec
    float a = b2[t];
    const float4* w2r = (const float4*)(W2 + (size_t)t * HID);
    const float4* smv = (const float4*)sm;
#pragma unroll 8
    for (int j = 0; j < HID / 4; ++j) {
        float4 wv = w2r[j], mv = smv[j];
        a = fmaf(wv.x, mv.x, a); a = fmaf(wv.y, mv.y, a);
        a = fmaf(wv.z, mv.z, a); a = fmaf(wv.w, mv.w, a);
    }
    smid[t] = a;
    __syncthreads();

    // Wfc matvec
    a = bfc[t];
    const float4* wfr  = (const float4*)(Wfc + (size_t)t * HID);
    const float4* smdv = (const float4*)smid;
#pragma unroll 8
    for (int j = 0; j < HID / 4; ++j) {
        float4 wv = wfr[j], mv = smdv[j];
        a = fmaf(wv.x, mv.x, a); a = fmaf(wv.y, mv.y, a);
        a = fmaf(wv.z, mv.z, a); a = fmaf(wv.w, mv.w, a);
    }
    sgcn[t] = a;

    // global branch
    if (t < OUTD) {
        float avg = (g_speedp[b * 4 + 0] + g_speedp[b * 4 + 1]
                   + g_speedp[b * 4 + 2] + g_speedp[b * 4 + 3]) * (1.0f / 1024.0f);
        float mx = g_maxp[b * 16];
#pragma unroll
        for (int k = 1; k < 16; ++k) mx = fmaxf(mx, g_maxp[b * 16 + k]);
        float den = rsqrtf(mx);
        sglo[t] = fmaxf(fmaf(Wg[t * 2], avg, fmaf(Wg[t * 2 + 1], den, bg[t])), 0.f);
    }
    __syncthreads();

    if (t < OUTD) {
        float o = bp[t];
        const float* wp = Wp + t * (MLPH + HID + OUTD);
#pragma unroll 8
        for (int j = 0; j < MLPH; ++j) o = fmaf(wp[j], sy1[j], o);
#pragma unroll 8
        for (int j = 0; j < HID;  ++j) o = fmaf(wp[MLPH + j], sgcn[j], o);
#pragma unroll
        for (int j = 0; j < OUTD; ++j) o = fmaf(wp[MLPH + HID + j], sglo[j], o);
        out[b * OUTD + t] = o;
    }
}

extern "C" void kernel_launch(void* const* d_in, const int* in_sizes, int n_in,
                              void* d_out, int out_size) {
    const float* x   = (const float*)d_in[0];
    const float* W1  = (const float*)d_in[1];
    const float* b1  = (const float*)d_in[2];
    const float* W2  = (const float*)d_in[3];
    const float* b2  = (const float*)d_in[4];
    const float* Wfc = (const float*)d_in[5];
    const float* bfc = (const float*)d_in[6];
    const float* Wg  = (const float*)d_in[7];
    const float* bg  = (const float*)d_in[8];
    const float* Wm0 = (const float*)d_in[9];
    const float* bm0 = (const float*)d_in[10];
    const float* Wm1 = (const float*)d_in[11];
    const float* bm1 = (const float*)d_in[12];
    const float* Wp  = (const float*)d_in[13];
    const float* bp  = (const float*)d_in[14];
    float* out = (float*)d_out;

    kA<<<576, 256>>>(x, Wm0);
    k2_gcn<<<128, 256>>>(x, W1, b1);
    k3_final<<<32, 256>>>(W2, b2, Wfc, bfc, Wg, bg, Wm1, bm1, bm0, Wp, bp, out);
}